// round 14
// baseline (speedup 1.0000x reference)
#include <cuda_runtime.h>
#include <cuda_bf16.h>
#include <cstdint>

#define B_SZ 8
#define C_SZ 512
#define NB   2048
#define DD   128

// ---------------- device scratch (allocation-free) ----------------
__device__ alignas(256) __nv_bfloat16 g_Yh [B_SZ * DD * NB];          // [b][d][n] hi
__device__ alignas(256) __nv_bfloat16 g_Yl [B_SZ * DD * NB];          // [b][d][n] lo
__device__ alignas(256) float         g_V  [B_SZ * DD * NB];          // [b][d][n]
__device__ alignas(256) __nv_bfloat16 g_Vsh[B_SZ * DD * NB];          // split(V/Z) hi
__device__ alignas(256) __nv_bfloat16 g_Vsl[B_SZ * DD * NB];          // split(V/Z) lo
__device__ alignas(256) uint32_t g_P32[(size_t)B_SZ * NB * NB];       // [b][n][m] {hi,lo} packed (symmetric)
__device__ alignas(16) float g_Z[B_SZ * NB];

// ---------------- helpers ----------------
__device__ __forceinline__ uint32_t smem_u32(const void* p) {
    uint32_t a;
    asm("{ .reg .u64 t; cvta.to.shared.u64 t, %1; cvt.u32.u64 %0, t; }" : "=r"(a) : "l"(p));
    return a;
}
__device__ __forceinline__ void cp16(uint32_t saddr, const void* gptr) {
    asm volatile("cp.async.cg.shared.global [%0], [%1], 16;"
                 :: "r"(saddr), "l"(__cvta_generic_to_global(gptr)) : "memory");
}
__device__ __forceinline__ void cp_commit() { asm volatile("cp.async.commit_group;" ::: "memory"); }
template <int N>
__device__ __forceinline__ void cp_wait() { asm volatile("cp.async.wait_group %0;" :: "n"(N) : "memory"); }

__device__ __forceinline__ void ldsm4(uint32_t* r, uint32_t addr) {
    asm volatile("ldmatrix.sync.aligned.m8n8.x4.shared.b16 {%0,%1,%2,%3}, [%4];"
                 : "=r"(r[0]), "=r"(r[1]), "=r"(r[2]), "=r"(r[3]) : "r"(addr));
}
__device__ __forceinline__ void ldsm4t(uint32_t* r, uint32_t addr) {
    asm volatile("ldmatrix.sync.aligned.m8n8.x4.trans.shared.b16 {%0,%1,%2,%3}, [%4];"
                 : "=r"(r[0]), "=r"(r[1]), "=r"(r[2]), "=r"(r[3]) : "r"(addr));
}
__device__ __forceinline__ void mma16816(float* c, const uint32_t* a, const uint32_t* b) {
    asm volatile("mma.sync.aligned.m16n8k16.row.col.f32.bf16.bf16.f32 "
                 "{%0,%1,%2,%3}, {%4,%5,%6,%7}, {%8,%9}, {%0,%1,%2,%3};"
                 : "+f"(c[0]), "+f"(c[1]), "+f"(c[2]), "+f"(c[3])
                 : "r"(a[0]), "r"(a[1]), "r"(a[2]), "r"(a[3]), "r"(b[0]), "r"(b[1]));
}
__device__ __forceinline__ uint32_t prmt(uint32_t a, uint32_t b, uint32_t s) {
    uint32_t r; asm("prmt.b32 %0, %1, %2, %3;" : "=r"(r) : "r"(a), "r"(b), "r"(s)); return r;
}
__device__ __forceinline__ void sts_v2(uint32_t addr, uint32_t a, uint32_t b) {
    asm volatile("st.shared.v2.b32 [%0], {%1,%2};" :: "r"(addr), "r"(a), "r"(b));
}

// fast exp (FMA pipe only)
__device__ __forceinline__ float fexp(float x) {
    float t  = x * 1.4426950408889634f;
    float z  = t + 12582912.0f;
    float fi = z - 12582912.0f;
    float f  = t - fi;
    int   e  = __float_as_int(z) - 0x4b400000;
    float p  = 1.33335581e-3f;
    p = fmaf(p, f, 9.61812911e-3f);
    p = fmaf(p, f, 5.55041087e-2f);
    p = fmaf(p, f, 2.40226507e-1f);
    p = fmaf(p, f, 6.93147181e-1f);
    p = fmaf(p, f, 1.0f);
    return __int_as_float(__float_as_int(p) + (int)((unsigned)e << 23));
}
__device__ __forceinline__ uint32_t split_pack(float p) {
    __nv_bfloat16 h = __float2bfloat16(p);
    __nv_bfloat16 l = __float2bfloat16(p - __bfloat162float(h));
    return (uint32_t)__bfloat16_as_ushort(h) | ((uint32_t)__bfloat16_as_ushort(l) << 16);
}
__device__ __forceinline__ unsigned short bf_hi(float v) {
    return __bfloat16_as_ushort(__float2bfloat16(v));
}
__device__ __forceinline__ unsigned short bf_lo(float v) {
    __nv_bfloat16 h = __float2bfloat16(v);
    return __bfloat16_as_ushort(__float2bfloat16(v - __bfloat162float(h)));
}

// ---------------------------------------------------------------------------
// K1 projection (HMMA split-bf16), W split fused — unchanged from R13.
// ---------------------------------------------------------------------------
#define P_SMEM 131072
__global__ __launch_bounds__(256) void proj_kernel(const float* __restrict__ x,
                                                   const float* __restrict__ wqk,
                                                   const float* __restrict__ wv,
                                                   const float* __restrict__ bv) {
    extern __shared__ char dsm[];
    const uint32_t sb = smem_u32(dsm);
    const uint32_t XS = sb;
    const uint32_t WS = sb + 65536;

    const int tid = threadIdx.x, lane = tid & 31, wid = tid >> 5;
    const int wy = wid >> 2, wx = wid & 3;
    const int lr = lane & 7;
    const int b = blockIdx.y, n0 = blockIdx.x * 128;
    const float* xb = x + (size_t)b * C_SZ * NB;

    auto load_x = [&](int t, float4* xr) {
#pragma unroll
        for (int i = 0; i < 8; i++) {
            int f4i = tid + 256 * i;
            int r = f4i >> 5, col4 = f4i & 31;
            xr[i] = *reinterpret_cast<const float4*>(&xb[(size_t)(t * 64 + r) * NB + n0 + col4 * 4]);
        }
    };
    auto sts_x = [&](int stage, const float4* xr) {
        uint32_t dh = XS + (uint32_t)stage * 32768, dl = dh + 16384;
#pragma unroll
        for (int i = 0; i < 8; i++) {
            int f4i = tid + 256 * i;
            int r = f4i >> 5, col4 = f4i & 31;
            float4 v = xr[i];
            uint32_t h01 = (uint32_t)bf_hi(v.x) | ((uint32_t)bf_hi(v.y) << 16);
            uint32_t h23 = (uint32_t)bf_hi(v.z) | ((uint32_t)bf_hi(v.w) << 16);
            uint32_t l01 = (uint32_t)bf_lo(v.x) | ((uint32_t)bf_lo(v.y) << 16);
            uint32_t l23 = (uint32_t)bf_lo(v.z) | ((uint32_t)bf_lo(v.w) << 16);
            int u = col4 >> 1;
            uint32_t off = (uint32_t)r * 256 +
                           (uint32_t)((((u & 7) ^ (r & 7)) | (u & 8)) * 16) +
                           (uint32_t)((col4 & 1) * 8);
            sts_v2(dh + off, h01, h23);
            sts_v2(dl + off, l01, l23);
        }
    };
    auto load_w = [&](const float* W, int t, float4* wr) {
        int c0 = t * 64;
#pragma unroll
        for (int i = 0; i < 8; i++) {
            int f4i = tid + 256 * i;
            int r = f4i >> 4, col4 = f4i & 15;
            wr[i] = *reinterpret_cast<const float4*>(&W[(size_t)r * C_SZ + c0 + col4 * 4]);
        }
    };
    auto sts_w = [&](int stage, const float4* wr) {
        uint32_t dh = WS + (uint32_t)stage * 32768, dl = dh + 16384;
#pragma unroll
        for (int i = 0; i < 8; i++) {
            int f4i = tid + 256 * i;
            int r = f4i >> 4, col4 = f4i & 15;
            float4 v = wr[i];
            uint32_t h01 = (uint32_t)bf_hi(v.x) | ((uint32_t)bf_hi(v.y) << 16);
            uint32_t h23 = (uint32_t)bf_hi(v.z) | ((uint32_t)bf_hi(v.w) << 16);
            uint32_t l01 = (uint32_t)bf_lo(v.x) | ((uint32_t)bf_lo(v.y) << 16);
            uint32_t l23 = (uint32_t)bf_lo(v.z) | ((uint32_t)bf_lo(v.w) << 16);
            int u = col4 >> 1;
            uint32_t off = (uint32_t)r * 128 +
                           (uint32_t)(((u ^ (r & 7)) * 16)) +
                           (uint32_t)((col4 & 1) * 8);
            sts_v2(dh + off, h01, h23);
            sts_v2(dl + off, l01, l23);
        }
    };

    float4 xr[8], wr[8];
#pragma unroll
    for (int pass = 0; pass < 2; pass++) {
        const float* W = pass ? wv : wqk;

        load_w(W, 0, wr); load_x(0, xr);
        sts_w(0, wr);     sts_x(0, xr);
        load_w(W, 1, wr); load_x(1, xr);
        sts_w(1, wr);     sts_x(1, xr);
        load_w(W, 2, wr); load_x(2, xr);

        float acc[4][4][4];
#pragma unroll
        for (int i = 0; i < 4; i++)
#pragma unroll
            for (int j = 0; j < 4; j++)
#pragma unroll
                for (int k = 0; k < 4; k++) acc[i][j][k] = 0.0f;

        for (int t = 0; t < 8; t++) {
            __syncthreads();
            const uint32_t ws = WS + (uint32_t)(t & 1) * 32768;
            const uint32_t xs = XS + (uint32_t)(t & 1) * 32768;
#pragma unroll
            for (int ks = 0; ks < 4; ks++) {
                uint32_t Ah[4][4], Al[4][4], Bh[4][2], Bl[4][2];
#pragma unroll
                for (int af = 0; af < 4; af++) {
                    int r = wy * 64 + af * 16 + ((lane >> 3) & 1) * 8 + lr;
                    int c16 = 2 * ks + ((lane >> 4) & 1);
                    uint32_t off = (uint32_t)r * 128 + (uint32_t)((c16 ^ (r & 7)) * 16);
                    ldsm4(Ah[af], ws + off);
                    ldsm4(Al[af], ws + 16384 + off);
                }
#pragma unroll
                for (int nf = 0; nf < 2; nf++) {
                    int row = 16 * ks + lr + ((lane >> 3) & 1) * 8;
                    int col = wx * 32 + nf * 16 + ((lane >> 4) & 1) * 8;
                    int u = col >> 3;
                    uint32_t off = (uint32_t)row * 256 +
                                   (uint32_t)((((u & 7) ^ (row & 7)) | (u & 8)) * 16);
                    uint32_t th[4], tl[4];
                    ldsm4t(th, xs + off);
                    ldsm4t(tl, xs + 16384 + off);
                    Bh[nf * 2][0] = th[0]; Bh[nf * 2][1] = th[1];
                    Bh[nf * 2 + 1][0] = th[2]; Bh[nf * 2 + 1][1] = th[3];
                    Bl[nf * 2][0] = tl[0]; Bl[nf * 2][1] = tl[1];
                    Bl[nf * 2 + 1][0] = tl[2]; Bl[nf * 2 + 1][1] = tl[3];
                }
#pragma unroll
                for (int af = 0; af < 4; af++)
#pragma unroll
                    for (int bf = 0; bf < 4; bf++) {
                        mma16816(acc[af][bf], Ah[af], Bh[bf]);
                        mma16816(acc[af][bf], Ah[af], Bl[bf]);
                        mma16816(acc[af][bf], Al[af], Bh[bf]);
                    }
            }
            __syncthreads();
            if (t + 2 < 8) {
                sts_w(t & 1, wr);
                sts_x(t & 1, xr);
                if (t + 3 < 8) { load_w(W, t + 3, wr); load_x(t + 3, xr); }
            }
        }
        if (pass == 0) {
            __nv_bfloat16* Yhb = g_Yh + (size_t)b * DD * NB;
            __nv_bfloat16* Ylb = g_Yl + (size_t)b * DD * NB;
#pragma unroll
            for (int af = 0; af < 4; af++)
#pragma unroll
                for (int h = 0; h < 2; h++) {
                    int d = wy * 64 + af * 16 + (lane >> 2) + 8 * h;
#pragma unroll
                    for (int bf = 0; bf < 4; bf++) {
                        int n = n0 + wx * 32 + bf * 8 + (lane & 3) * 2;
                        float y0 = acc[af][bf][2 * h], y1 = acc[af][bf][2 * h + 1];
                        uint32_t hw = (uint32_t)bf_hi(y0) | ((uint32_t)bf_hi(y1) << 16);
                        uint32_t lw = (uint32_t)bf_lo(y0) | ((uint32_t)bf_lo(y1) << 16);
                        *reinterpret_cast<uint32_t*>(&Yhb[(size_t)d * NB + n]) = hw;
                        *reinterpret_cast<uint32_t*>(&Ylb[(size_t)d * NB + n]) = lw;
                    }
                }
        } else {
            float* Vb = g_V + (size_t)b * DD * NB;
#pragma unroll
            for (int af = 0; af < 4; af++)
#pragma unroll
                for (int h = 0; h < 2; h++) {
                    int d = wy * 64 + af * 16 + (lane >> 2) + 8 * h;
                    float bias = bv[d];
#pragma unroll
                    for (int bf = 0; bf < 4; bf++) {
                        int n = n0 + wx * 32 + bf * 8 + (lane & 3) * 2;
                        *reinterpret_cast<float2*>(&Vb[(size_t)d * NB + n]) =
                            make_float2(acc[af][bf][0 + 2 * h] + bias,
                                        acc[af][bf][1 + 2 * h] + bias);
                    }
                }
        }
        if (pass == 0) __syncthreads();
    }
}

// ---------------------------------------------------------------------------
// K2: SYMMETRIC energy — now 2 CTAs/SM so epilogue overlaps a co-resident
// CTA's MMA mainloop.
// ---------------------------------------------------------------------------
#define E_SMEM 65536
__global__ __launch_bounds__(256, 2) void energy_kernel() {
    extern __shared__ char dsm[];
    const uint32_t sb = smem_u32(dsm);
    __shared__ float zrow[128], zcol[128];

    const int tid = threadIdx.x, lane = tid & 31, wid = tid >> 5;
    const int wy = wid >> 2, wx = wid & 3;
    const int lr = lane & 7;
    const int b = blockIdx.y;

    int nt = 0, rem = blockIdx.x;
    while (rem >= 16 - nt) { rem -= 16 - nt; nt++; }
    const int mt = nt + rem;
    const int n0 = nt * 128, m0 = mt * 128;
    const bool offdiag = (nt != mt);

    const __nv_bfloat16* Yh = g_Yh + (size_t)b * DD * NB;
    const __nv_bfloat16* Yl = g_Yl + (size_t)b * DD * NB;

    if (tid < 128) { zrow[tid] = 0.0f; zcol[tid] = 0.0f; }

    auto cp_chunk = [&](uint32_t dst, const __nv_bfloat16* src, int col0, int d0) {
#pragma unroll
        for (int k = 0; k < 2; k++) {
            int idx = tid + 256 * k;
            int r = idx >> 4, c = idx & 15;
            uint32_t sw = (uint32_t)(((c & 7) ^ (r & 7)) | (c & 8));
            cp16(dst + (uint32_t)r * 256 + sw * 16,
                 src + (size_t)(d0 + r) * NB + col0 + c * 8);
        }
    };
    auto load_chunk = [&](int t) {
        uint32_t st = sb + (uint32_t)(t & 1) * 32768;
        int d0 = t * 32;
        cp_chunk(st,         Yh, n0, d0);
        cp_chunk(st + 8192,  Yl, n0, d0);
        cp_chunk(st + 16384, Yh, m0, d0);
        cp_chunk(st + 24576, Yl, m0, d0);
        cp_commit();
    };

    load_chunk(0);
    load_chunk(1);

    float acc[4][4][4];
#pragma unroll
    for (int i = 0; i < 4; i++)
#pragma unroll
        for (int j = 0; j < 4; j++)
#pragma unroll
            for (int k = 0; k < 4; k++) acc[i][j][k] = 0.0f;

    for (int t = 0; t < 4; t++) {
        if (t == 3) cp_wait<0>(); else cp_wait<1>();
        __syncthreads();
        const uint32_t st = sb + (uint32_t)(t & 1) * 32768;
        const uint32_t Ahs = st, Als = st + 8192, Bhs = st + 16384, Bls = st + 24576;
#pragma unroll
        for (int ks = 0; ks < 2; ks++) {
            uint32_t Ah[4][4], Al[4][4], Bh[4][2], Bl[4][2];
#pragma unroll
            for (int af = 0; af < 4; af++) {
                int row = 16 * ks + lr + ((lane >> 4) & 1) * 8;
                int col = wy * 64 + af * 16 + ((lane >> 3) & 1) * 8;
                int u = col >> 3;
                uint32_t off = (uint32_t)row * 256 +
                               (uint32_t)((((u & 7) ^ (row & 7)) | (u & 8)) * 16);
                ldsm4t(Ah[af], Ahs + off);
                ldsm4t(Al[af], Als + off);
            }
#pragma unroll
            for (int nf = 0; nf < 2; nf++) {
                int row = 16 * ks + lr + ((lane >> 3) & 1) * 8;
                int col = wx * 32 + nf * 16 + ((lane >> 4) & 1) * 8;
                int u = col >> 3;
                uint32_t off = (uint32_t)row * 256 +
                               (uint32_t)((((u & 7) ^ (row & 7)) | (u & 8)) * 16);
                uint32_t th[4], tl[4];
                ldsm4t(th, Bhs + off);
                ldsm4t(tl, Bls + off);
                Bh[nf * 2][0] = th[0]; Bh[nf * 2][1] = th[1];
                Bh[nf * 2 + 1][0] = th[2]; Bh[nf * 2 + 1][1] = th[3];
                Bl[nf * 2][0] = tl[0]; Bl[nf * 2][1] = tl[1];
                Bl[nf * 2 + 1][0] = tl[2]; Bl[nf * 2 + 1][1] = tl[3];
            }
#pragma unroll
            for (int af = 0; af < 4; af++)
#pragma unroll
                for (int bf = 0; bf < 4; bf++) {
                    mma16816(acc[af][bf], Ah[af], Bh[bf]);
                    mma16816(acc[af][bf], Ah[af], Bl[bf]);
                    mma16816(acc[af][bf], Al[af], Bh[bf]);
                }
        }
        __syncthreads();
        if (t + 2 < 4) load_chunk(t + 2);
    }

    const float INVS = 0.08838834764831845f;
    uint32_t* P32 = g_P32 + (size_t)b * NB * NB;
    float zr[4][2], zc[4][2];
#pragma unroll
    for (int i = 0; i < 4; i++) { zr[i][0] = zr[i][1] = zc[i][0] = zc[i][1] = 0.0f; }

#pragma unroll
    for (int af = 0; af < 4; af++) {
        int rloc = wy * 64 + af * 16 + (lane >> 2);
#pragma unroll
        for (int h = 0; h < 2; h++) {
            int rr = n0 + rloc + 8 * h;
#pragma unroll
            for (int bf = 0; bf < 4; bf++) {
                float p0 = fexp(acc[af][bf][2 * h + 0] * INVS);
                float p1 = fexp(acc[af][bf][2 * h + 1] * INVS);
                zr[af][h] += p0 + p1;
                zc[bf][0] += p0; zc[bf][1] += p1;
                int mloc = wx * 32 + bf * 8 + (lane & 3) * 2;
                uint32_t w0 = split_pack(p0), w1 = split_pack(p1);
                *reinterpret_cast<uint2*>(P32 + (size_t)rr * NB + m0 + mloc) =
                    make_uint2(w0, w1);
                if (offdiag) {
                    P32[(size_t)(m0 + mloc) * NB + rr]     = w0;
                    P32[(size_t)(m0 + mloc + 1) * NB + rr] = w1;
                }
            }
        }
    }
#pragma unroll
    for (int af = 0; af < 4; af++)
#pragma unroll
        for (int h = 0; h < 2; h++) {
            float v = zr[af][h];
            v += __shfl_xor_sync(0xffffffffu, v, 1);
            v += __shfl_xor_sync(0xffffffffu, v, 2);
            if ((lane & 3) == 0)
                atomicAdd(&zrow[wy * 64 + af * 16 + (lane >> 2) + 8 * h], v);
        }
#pragma unroll
    for (int bf = 0; bf < 4; bf++)
#pragma unroll
        for (int k = 0; k < 2; k++) {
            float v = zc[bf][k];
            v += __shfl_xor_sync(0xffffffffu, v, 4);
            v += __shfl_xor_sync(0xffffffffu, v, 8);
            v += __shfl_xor_sync(0xffffffffu, v, 16);
            if (lane < 4)
                atomicAdd(&zcol[wx * 32 + bf * 8 + (lane & 3) * 2 + k], v);
        }
    __syncthreads();
    if (tid < 128) {
        atomicAdd(&g_Z[b * NB + n0 + tid], zrow[tid]);
        if (offdiag) atomicAdd(&g_Z[b * NB + m0 + tid], zcol[tid]);
    }
}

// ---------------------------------------------------------------------------
// K3: Vs = split(V / Z)
// ---------------------------------------------------------------------------
__global__ __launch_bounds__(256) void vsplit_kernel() {
    int i = blockIdx.x * 256 + threadIdx.x;
    float4 v = reinterpret_cast<const float4*>(g_V)[i];
    int n4 = (i & 511) << 2;
    int b  = i >> 16;
    float4 zz = *reinterpret_cast<const float4*>(&g_Z[(b << 11) + n4]);
    float y0 = v.x / zz.x, y1 = v.y / zz.y, y2 = v.z / zz.z, y3 = v.w / zz.w;
    uint2 hw, lw;
    hw.x = (uint32_t)bf_hi(y0) | ((uint32_t)bf_hi(y1) << 16);
    hw.y = (uint32_t)bf_hi(y2) | ((uint32_t)bf_hi(y3) << 16);
    lw.x = (uint32_t)bf_lo(y0) | ((uint32_t)bf_lo(y1) << 16);
    lw.y = (uint32_t)bf_lo(y2) | ((uint32_t)bf_lo(y3) << 16);
    reinterpret_cast<uint2*>(g_Vsh)[i] = hw;
    reinterpret_cast<uint2*>(g_Vsl)[i] = lw;
}

// ---------------------------------------------------------------------------
// K4: out[d][m] = sum_n Vs[d][n] * P(m,n).  m-tile 64, 2 CTAs/SM.
// ldgB hoisted above the wait/sync to stretch LDG latency over the chunk.
// ---------------------------------------------------------------------------
#define O_SMEM 98304
__global__ __launch_bounds__(256, 2) void out_kernel(float* __restrict__ out) {
    extern __shared__ char dsm[];
    const uint32_t sb = smem_u32(dsm);
    const uint32_t Ab = sb, Bb = sb + 65536;

    const int tid = threadIdx.x, lane = tid & 31, wid = tid >> 5;
    const int wy = wid >> 2, wx = wid & 3;
    const int g = lane >> 3, lr = lane & 7;
    const int b = blockIdx.y, m0 = blockIdx.x * 64;
    const __nv_bfloat16* Vh = g_Vsh + (size_t)b * DD * NB;
    const __nv_bfloat16* Vl = g_Vsl + (size_t)b * DD * NB;
    const uint32_t* Pb = g_P32 + (size_t)b * NB * NB;

    auto cpA = [&](int t) {
        uint32_t dst = Ab + (uint32_t)(t & 1) * 32768;
        int nk = t * 64;
#pragma unroll
        for (int i = 0; i < 4; i++) {
            int idx = tid + 256 * i;
            int r = idx >> 3, c = idx & 7;
            uint32_t off = (uint32_t)r * 128 + (uint32_t)((c ^ (r & 7)) * 16);
            cp16(dst + off,         (const char*)(Vh + (size_t)r * NB + nk) + c * 16);
            cp16(dst + 16384 + off, (const char*)(Vl + (size_t)r * NB + nk) + c * 16);
        }
    };
    auto stsB = [&](int stage, const uint4* w) {
        uint32_t Bd = Bb + (uint32_t)stage * 16384;
#pragma unroll
        for (int i = 0; i < 4; i++) {
            int idx = tid + 256 * i;
            int r = idx >> 4, cu = idx & 15;
            uint32_t a = Bd + (uint32_t)r * 128 +
                         (uint32_t)((((cu >> 1) ^ (r & 7)) * 16) + (cu & 1) * 8);
            sts_v2(a,        prmt(w[i].x, w[i].y, 0x5410), prmt(w[i].z, w[i].w, 0x5410));
            sts_v2(a + 8192, prmt(w[i].x, w[i].y, 0x7632), prmt(w[i].z, w[i].w, 0x7632));
        }
    };
    auto ldgB = [&](int t, uint4* w) {
#pragma unroll
        for (int i = 0; i < 4; i++) {
            int idx = tid + 256 * i;
            int r = idx >> 4, cu = idx & 15;
            w[i] = *(reinterpret_cast<const uint4*>(Pb + (size_t)(m0 + r) * NB + t * 64) + cu);
        }
    };

    cpA(0); cp_commit();
    cpA(1); cp_commit();
    {
        uint4 w[4];
        ldgB(0, w);
        stsB(0, w);
    }

    float acc[4][2][4];
#pragma unroll
    for (int i = 0; i < 4; i++)
#pragma unroll
        for (int j = 0; j < 2; j++)
#pragma unroll
            for (int k = 0; k < 4; k++) acc[i][j][k] = 0.0f;

    for (int t = 0; t < 32; t++) {
        const uint32_t As = Ab + (uint32_t)(t & 1) * 32768;
        const uint32_t Bs = Bb + (uint32_t)(t & 1) * 16384;

        uint4 lb[4];
        if (t + 1 < 32) ldgB(t + 1, lb);      // hoisted: LDG in flight across wait+sync+mma

        if (t == 31) cp_wait<0>(); else cp_wait<1>();
        __syncthreads();

#pragma unroll
        for (int ks = 0; ks < 4; ks++) {
            uint32_t Ah[4][4], Al[4][4], Bh[4], Bl[4];
#pragma unroll
            for (int af = 0; af < 4; af++) {
                int r = wy * 64 + af * 16 + (g & 1) * 8 + lr;
                int c = 2 * ks + (g >> 1);
                uint32_t off = (uint32_t)r * 128 + (uint32_t)((c ^ (r & 7)) * 16);
                ldsm4(Ah[af], As + off);
                ldsm4(Al[af], As + 16384 + off);
            }
            {
                int r = wx * 16 + (g >> 1) * 8 + lr;
                int c = 2 * ks + (g & 1);
                uint32_t off = (uint32_t)r * 128 + (uint32_t)((c ^ (r & 7)) * 16);
                ldsm4(Bh, Bs + off);
                ldsm4(Bl, Bs + 8192 + off);
            }
#pragma unroll
            for (int af = 0; af < 4; af++)
#pragma unroll
                for (int bf = 0; bf < 2; bf++) {
                    uint32_t bH[2] = { Bh[bf * 2], Bh[bf * 2 + 1] };
                    uint32_t bL[2] = { Bl[bf * 2], Bl[bf * 2 + 1] };
                    mma16816(acc[af][bf], Ah[af], bH);
                    mma16816(acc[af][bf], Ah[af], bL);
                    mma16816(acc[af][bf], Al[af], bH);
                }
        }
        __syncthreads();
        if (t + 1 < 32) stsB((t + 1) & 1, lb);
        if (t + 2 < 32) { cpA(t + 2); cp_commit(); }
    }
#pragma unroll
    for (int af = 0; af < 4; af++) {
        int d = wy * 64 + af * 16 + (lane >> 2);
#pragma unroll
        for (int bf = 0; bf < 2; bf++) {
            int m = m0 + wx * 16 + bf * 8 + (lane & 3) * 2;
            *reinterpret_cast<float2*>(&out[((size_t)b * DD + d) * NB + m]) =
                make_float2(acc[af][bf][0], acc[af][bf][1]);
            *reinterpret_cast<float2*>(&out[((size_t)b * DD + d + 8) * NB + m]) =
                make_float2(acc[af][bf][2], acc[af][bf][3]);
        }
    }
}

// ---------------------------------------------------------------------------
extern "C" void kernel_launch(void* const* d_in, const int* in_sizes, int n_in,
                              void* d_out, int out_size) {
    (void)in_sizes; (void)n_in; (void)out_size;
    const float* x   = (const float*)d_in[0];
    const float* wqk = (const float*)d_in[1];
    const float* wv  = (const float*)d_in[2];
    const float* bv  = (const float*)d_in[3];
    float* out = (float*)d_out;

    cudaFuncSetAttribute(proj_kernel,   cudaFuncAttributeMaxDynamicSharedMemorySize, P_SMEM);
    cudaFuncSetAttribute(energy_kernel, cudaFuncAttributeMaxDynamicSharedMemorySize, E_SMEM);
    cudaFuncSetAttribute(out_kernel,    cudaFuncAttributeMaxDynamicSharedMemorySize, O_SMEM);

    void* zaddr = nullptr;
    cudaGetSymbolAddress(&zaddr, g_Z);
    cudaMemsetAsync(zaddr, 0, sizeof(float) * B_SZ * NB, 0);

    proj_kernel<<<dim3(NB / 128, B_SZ), 256, P_SMEM>>>(x, wqk, wv, bv);
    energy_kernel<<<dim3(136, B_SZ), 256, E_SMEM>>>();
    vsplit_kernel<<<B_SZ * DD * NB / 4 / 256, 256>>>();
    out_kernel<<<dim3(NB / 64, B_SZ), 256, O_SMEM>>>(out);
}